// round 10
// baseline (speedup 1.0000x reference)
#include <cuda_runtime.h>
#include <cuda_bf16.h>

#define BATCH 4
#define SEQ   2048
#define EMB   1024
#define HD    128
#define BTOT  (BATCH*SEQ)

#define NQT      32          // q tiles per batch (BQ=64)
#define CHTILES  8           // kv tiles (of 64) per chunk = 512 keys
#define MAXCH    4           // max chunks per q tile
#define NKT      (EMB/32)    // k-tiles in QKV GEMM = 32

// ---------------- device scratch (allocation-free rule) ----------------
__device__ float g_Q[BTOT * HD];   // full fp32
__device__ float g_K[BTOT * HD];   // full fp32
__device__ float g_V[BTOT * HD];   // full fp32
// split-KV partials: slot = ((b*NQT + qt)*MAXCH + c)
__device__ float g_pO[(size_t)BATCH * NQT * MAXCH * 64 * HD];
__device__ float g_pm[BATCH * NQT * MAXCH * 64];
__device__ float g_pl[BATCH * NQT * MAXCH * 64];

__device__ __forceinline__ unsigned f2tf(float f) {
    unsigned u;
    asm("cvt.rna.tf32.f32 %0, %1;" : "=r"(u) : "f"(f));
    return u;
}

// 3xTF32 split: v = hi + lo to ~2^-22 relative
__device__ __forceinline__ void split3(float v, unsigned& hi, unsigned& lo) {
    unsigned h = f2tf(v);
    float r = v - __uint_as_float(h);   // exact in fp32
    hi = h;
    lo = f2tf(r);
}

__device__ __forceinline__ void cp_async16(void* smem_dst, const void* gmem_src) {
    unsigned s = (unsigned)__cvta_generic_to_shared(smem_dst);
    asm volatile("cp.async.cg.shared.global [%0], [%1], 16;\n" :: "r"(s), "l"(gmem_src));
}
__device__ __forceinline__ void cp_commit() {
    asm volatile("cp.async.commit_group;\n");
}
template<int N> __device__ __forceinline__ void cp_wait() {
    asm volatile("cp.async.wait_group %0;\n" :: "n"(N) : "memory");
}

// mma.sync m16n8k8 tf32: A row-major 16x8, B col-major 8x8, C fp32 16x8
__device__ __forceinline__ void mma_tf32(float* c, const unsigned* a, unsigned b0, unsigned b1) {
    asm volatile(
        "mma.sync.aligned.m16n8k8.row.col.f32.tf32.tf32.f32 "
        "{%0,%1,%2,%3}, {%4,%5,%6,%7}, {%8,%9}, {%0,%1,%2,%3};\n"
        : "+f"(c[0]), "+f"(c[1]), "+f"(c[2]), "+f"(c[3])
        : "r"(a[0]), "r"(a[1]), "r"(a[2]), "r"(a[3]), "r"(b0), "r"(b1));
}

// 3xTF32 compensated MMA: c += a*b with a = ah+al, b = bh+bl (al*bl dropped)
__device__ __forceinline__ void mma3(float* c, const unsigned* ah, const unsigned* al,
                                     unsigned bh0, unsigned bh1, unsigned bl0, unsigned bl1) {
    mma_tf32(c, al, bh0, bh1);
    mma_tf32(c, ah, bl0, bl1);
    mma_tf32(c, ah, bh0, bh1);
}

// ---------------------------------------------------------------------------
// Kernel 1: QKV projection, 3xTF32. Tile 128(M) x 128(N), K-chunk 32,
// cp.async double-buffered fp32 staging; hi/lo split at fragment load.
// 256 threads = 8 warps (4x2). blockIdx.y selects Q/K/V. Outputs full fp32.
// ---------------------------------------------------------------------------
#define XS 36
#define WS 132
#define QKV_SMEM ((2*128*XS + 2*32*WS) * 4)   // 70656 B

__global__ void __launch_bounds__(256, 2)
qkv_kernel(const float* __restrict__ x,
           const float* __restrict__ Wq, const float* __restrict__ bq,
           const float* __restrict__ Wk, const float* __restrict__ bk,
           const float* __restrict__ Wv, const float* __restrict__ bv)
{
    extern __shared__ float qsm[];
    float (*xs)[128][XS] = reinterpret_cast<float(*)[128][XS]>(qsm);
    float (*ws)[32][WS]  = reinterpret_cast<float(*)[32][WS]>(qsm + 2 * 128 * XS);

    const float* W; const float* bias; float* out;
    if (blockIdx.y == 0)      { W = Wq; bias = bq; out = g_Q; }
    else if (blockIdx.y == 1) { W = Wk; bias = bk; out = g_K; }
    else                      { W = Wv; bias = bv; out = g_V; }

    const int tid  = threadIdx.x;
    const int lane = tid & 31;
    const int warp = tid >> 5;
    const int wm   = warp >> 1;
    const int wn   = warp & 1;
    const int g    = lane >> 2;
    const int t    = lane & 3;
    const int m0   = blockIdx.x * 128;

    float acc[2][8][4];
#pragma unroll
    for (int i = 0; i < 2; i++)
#pragma unroll
        for (int j = 0; j < 8; j++)
#pragma unroll
            for (int k = 0; k < 4; k++) acc[i][j][k] = 0.f;

    auto stage = [&](int kt, int bf) {
        const int kk = kt * 32;
#pragma unroll
        for (int j = 0; j < 4; j++) {
            int idx = tid + j * 256;
            int r = idx >> 3, c4 = (idx & 7) * 4;
            cp_async16(&xs[bf][r][c4], &x[(size_t)(m0 + r) * EMB + kk + c4]);
        }
#pragma unroll
        for (int j = 0; j < 4; j++) {
            int idx = tid + j * 256;
            int r = idx >> 5, c4 = (idx & 31) * 4;
            cp_async16(&ws[bf][r][c4], &W[(size_t)(kk + r) * HD + c4]);
        }
        cp_commit();
    };

    stage(0, 0);
    int buf = 0;

    for (int kt = 0; kt < NKT; kt++) {
        if (kt + 1 < NKT) { stage(kt + 1, buf ^ 1); cp_wait<1>(); }
        else              { cp_wait<0>(); }
        __syncthreads();

#pragma unroll
        for (int ks = 0; ks < 32; ks += 8) {
            unsigned ah[2][4], al[2][4];
#pragma unroll
            for (int mt = 0; mt < 2; mt++) {
                int rm = wm * 32 + mt * 16;
                split3(xs[buf][rm + g    ][ks + t    ], ah[mt][0], al[mt][0]);
                split3(xs[buf][rm + g + 8][ks + t    ], ah[mt][1], al[mt][1]);
                split3(xs[buf][rm + g    ][ks + t + 4], ah[mt][2], al[mt][2]);
                split3(xs[buf][rm + g + 8][ks + t + 4], ah[mt][3], al[mt][3]);
            }
#pragma unroll
            for (int nt = 0; nt < 8; nt++) {
                int n = wn * 64 + nt * 8 + g;
                unsigned bh0, bl0, bh1, bl1;
                split3(ws[buf][ks + t    ][n], bh0, bl0);
                split3(ws[buf][ks + t + 4][n], bh1, bl1);
                mma3(acc[0][nt], ah[0], al[0], bh0, bh1, bl0, bl1);
                mma3(acc[1][nt], ah[1], al[1], bh0, bh1, bl0, bl1);
            }
        }
        __syncthreads();
        buf ^= 1;
    }

#pragma unroll
    for (int mt = 0; mt < 2; mt++) {
#pragma unroll
        for (int nt = 0; nt < 8; nt++) {
            int row = m0 + wm * 32 + mt * 16 + g;
            int col = wn * 64 + nt * 8 + t * 2;
            float b0 = bias[col], b1 = bias[col + 1];
            out[(size_t)row * HD + col]           = acc[mt][nt][0] + b0;
            out[(size_t)row * HD + col + 1]       = acc[mt][nt][1] + b1;
            out[(size_t)(row + 8) * HD + col]     = acc[mt][nt][2] + b0;
            out[(size_t)(row + 8) * HD + col + 1] = acc[mt][nt][3] + b1;
        }
    }
}

// ---------------------------------------------------------------------------
// Kernel 2: split-KV causal flash attention chunk, 3xTF32. BQ=64, BK=64.
// Grid (NQT, MAXCH, BATCH); ch > qt/8 exits. 128 threads (4 warps).
// Q staged once in smem (fp32); K/V staged per tile (fp32); hi/lo split at
// fragment load. P (fp32) overlays the K smem region: K fully consumed by
// the S-phase; a block barrier separates last K read from first P write.
// Smem: K/P 64x132 | V 64x136 | Q 64x132 = 102400 B. Occupancy 2.
// ---------------------------------------------------------------------------
#define KS 132
#define VS 136
#define PS 68
#define ATTN_SMEM ((64*KS + 64*VS + 64*KS) * 4)   // 102400 B

__global__ void __launch_bounds__(128, 2)
attn_kernel()
{
    const int qt = blockIdx.x;
    const int ch = blockIdx.y;
    const int b  = blockIdx.z;
    if (ch > (qt >> 3)) return;   // nch = qt/8 + 1

    extern __shared__ float sm[];
    float (*Ksm)[KS] = reinterpret_cast<float(*)[KS]>(sm);
    float (*Psm)[PS] = reinterpret_cast<float(*)[PS]>(sm);              // overlays K
    float (*Vsm)[VS] = reinterpret_cast<float(*)[VS]>(sm + 64 * KS);
    float (*Qsm)[KS] = reinterpret_cast<float(*)[KS]>(sm + 64 * KS + 64 * VS);

    const int q0    = qt * 64;
    const int kt0   = ch * CHTILES;
    const int ktend = min(kt0 + CHTILES, qt + 1);

    const int tid = threadIdx.x, lane = tid & 31, w = tid >> 5;
    const int g = lane >> 2, t = lane & 3;
    const float scale = 0.08838834764831845f;  // 1/sqrt(128)

    // stage Q tile once (fp32)
    {
        const float* Qg = g_Q + (size_t)(b * SEQ + q0) * HD;
        for (int j = tid; j < 2048; j += 128) {
            int r = j >> 5, c4 = (j & 31) * 4;
            cp_async16(&Qsm[r][c4], &Qg[(size_t)r * HD + c4]);
        }
        cp_commit();
    }

    float m_i[2] = { -1e30f, -1e30f };
    float l_i[2] = { 0.f, 0.f };
    float o[16][4];
#pragma unroll
    for (int i = 0; i < 16; i++)
#pragma unroll
        for (int j = 0; j < 4; j++) o[i][j] = 0.f;

    const float* Kp = g_K + (size_t)(b * SEQ) * HD;
    const float* Vp = g_V + (size_t)(b * SEQ) * HD;

    for (int kt = kt0; kt < ktend; kt++) {
        const int kv0 = kt * 64;
        __syncthreads();   // prior-iteration P/V reads complete before restage
        for (int j = tid; j < 2048; j += 128) {
            int r = j >> 5, c4 = (j & 31) * 4;
            cp_async16(&Ksm[r][c4], &Kp[(size_t)(kv0 + r) * HD + c4]);
            cp_async16(&Vsm[r][c4], &Vp[(size_t)(kv0 + r) * HD + c4]);
        }
        cp_commit();
        cp_wait<0>();      // also covers the Q stage on the first iteration
        __syncthreads();

        // ---- S = Q @ K^T (3xTF32), 16 x 64 per warp ----
        float s[8][4];
#pragma unroll
        for (int nt = 0; nt < 8; nt++)
#pragma unroll
            for (int j = 0; j < 4; j++) s[nt][j] = 0.f;

#pragma unroll
        for (int kc = 0; kc < 16; kc++) {
            const int d0 = kc * 8 + t;
            unsigned ah[4], al[4];
            split3(Qsm[w * 16 + g    ][d0    ], ah[0], al[0]);
            split3(Qsm[w * 16 + g + 8][d0    ], ah[1], al[1]);
            split3(Qsm[w * 16 + g    ][d0 + 4], ah[2], al[2]);
            split3(Qsm[w * 16 + g + 8][d0 + 4], ah[3], al[3]);
#pragma unroll
            for (int nt = 0; nt < 8; nt++) {
                const int key = nt * 8 + g;
                unsigned bh0, bl0, bh1, bl1;
                split3(Ksm[key][d0    ], bh0, bl0);
                split3(Ksm[key][d0 + 4], bh1, bl1);
                mma3(s[nt], ah, al, bh0, bh1, bl0, bl1);
            }
        }

        // apply softmax scale
#pragma unroll
        for (int nt = 0; nt < 8; nt++) {
            s[nt][0] *= scale; s[nt][1] *= scale;
            s[nt][2] *= scale; s[nt][3] *= scale;
        }

        // causal mask on the diagonal tile
        if (kt == qt) {
            int qr = q0 + w * 16 + g;
#pragma unroll
            for (int nt = 0; nt < 8; nt++) {
                int kc0 = kv0 + nt * 8 + t * 2;
                if (kc0     > qr)     s[nt][0] = -1e30f;
                if (kc0 + 1 > qr)     s[nt][1] = -1e30f;
                if (kc0     > qr + 8) s[nt][2] = -1e30f;
                if (kc0 + 1 > qr + 8) s[nt][3] = -1e30f;
            }
        }

        // online softmax
        float mx0 = -1e30f, mx1 = -1e30f;
#pragma unroll
        for (int nt = 0; nt < 8; nt++) {
            mx0 = fmaxf(mx0, fmaxf(s[nt][0], s[nt][1]));
            mx1 = fmaxf(mx1, fmaxf(s[nt][2], s[nt][3]));
        }
        mx0 = fmaxf(mx0, __shfl_xor_sync(0xffffffffu, mx0, 1));
        mx0 = fmaxf(mx0, __shfl_xor_sync(0xffffffffu, mx0, 2));
        mx1 = fmaxf(mx1, __shfl_xor_sync(0xffffffffu, mx1, 1));
        mx1 = fmaxf(mx1, __shfl_xor_sync(0xffffffffu, mx1, 2));

        float mn0 = fmaxf(m_i[0], mx0);
        float mn1 = fmaxf(m_i[1], mx1);
        float a0 = __expf(m_i[0] - mn0);
        float a1 = __expf(m_i[1] - mn1);
        m_i[0] = mn0; m_i[1] = mn1;

        float rs0 = 0.f, rs1 = 0.f;
#pragma unroll
        for (int nt = 0; nt < 8; nt++) {
            s[nt][0] = __expf(s[nt][0] - mn0);
            s[nt][1] = __expf(s[nt][1] - mn0);
            s[nt][2] = __expf(s[nt][2] - mn1);
            s[nt][3] = __expf(s[nt][3] - mn1);
            rs0 += s[nt][0] + s[nt][1];
            rs1 += s[nt][2] + s[nt][3];
        }
        rs0 += __shfl_xor_sync(0xffffffffu, rs0, 1);
        rs0 += __shfl_xor_sync(0xffffffffu, rs0, 2);
        rs1 += __shfl_xor_sync(0xffffffffu, rs1, 1);
        rs1 += __shfl_xor_sync(0xffffffffu, rs1, 2);
        l_i[0] = l_i[0] * a0 + rs0;
        l_i[1] = l_i[1] * a1 + rs1;

#pragma unroll
        for (int nt2 = 0; nt2 < 16; nt2++) {
            o[nt2][0] *= a0; o[nt2][1] *= a0;
            o[nt2][2] *= a1; o[nt2][3] *= a1;
        }

        // All warps done reading K before P overwrites the region
        __syncthreads();

        // P -> smem (warp-private rows), FULL fp32
        {
            int pr = w * 16 + g;
#pragma unroll
            for (int nt = 0; nt < 8; nt++) {
                int pc = nt * 8 + t * 2;
                Psm[pr    ][pc    ] = s[nt][0];
                Psm[pr    ][pc + 1] = s[nt][1];
                Psm[pr + 8][pc    ] = s[nt][2];
                Psm[pr + 8][pc + 1] = s[nt][3];
            }
        }
        __syncwarp();

        // ---- O += P @ V (3xTF32) ----
#pragma unroll
        for (int cc = 0; cc < 8; cc++) {
            const int pk = cc * 8 + t;
            unsigned pah[4], pal[4];
            split3(Psm[w * 16 + g    ][pk    ], pah[0], pal[0]);
            split3(Psm[w * 16 + g + 8][pk    ], pah[1], pal[1]);
            split3(Psm[w * 16 + g    ][pk + 4], pah[2], pal[2]);
            split3(Psm[w * 16 + g + 8][pk + 4], pah[3], pal[3]);
#pragma unroll
            for (int nt2 = 0; nt2 < 16; nt2++) {
                const int d = nt2 * 8 + g;
                unsigned bh0, bl0, bh1, bl1;
                split3(Vsm[cc * 8 + t    ][d], bh0, bl0);
                split3(Vsm[cc * 8 + t + 4][d], bh1, bl1);
                mma3(o[nt2], pah, pal, bh0, bh1, bl0, bl1);
            }
        }
        __syncwarp();
    }

    // write partials (unnormalized O, plus m and l)
    const int slot = (b * NQT + qt) * MAXCH + ch;
    float* pO = g_pO + (size_t)slot * 64 * HD;
#pragma unroll
    for (int nt2 = 0; nt2 < 16; nt2++) {
        int col = nt2 * 8 + t * 2;
        int r0 = w * 16 + g;
        pO[(size_t)r0 * HD + col]           = o[nt2][0];
        pO[(size_t)r0 * HD + col + 1]       = o[nt2][1];
        pO[(size_t)(r0 + 8) * HD + col]     = o[nt2][2];
        pO[(size_t)(r0 + 8) * HD + col + 1] = o[nt2][3];
    }
    if (t == 0) {
        g_pm[slot * 64 + w * 16 + g]     = m_i[0];
        g_pm[slot * 64 + w * 16 + g + 8] = m_i[1];
        g_pl[slot * 64 + w * 16 + g]     = l_i[0];
        g_pl[slot * 64 + w * 16 + g + 8] = l_i[1];
    }
}

// ---------------------------------------------------------------------------
// Kernel 3: merge split-KV partials for ALL q tiles. One block per (b, qt).
// out = sum_c exp(m_c - M) * O_c / sum_c exp(m_c - M) * l_c
// ---------------------------------------------------------------------------
__global__ void __launch_bounds__(128)
merge_kernel(float* __restrict__ out)
{
    const int b  = blockIdx.x >> 5;
    const int qt = blockIdx.x & 31;
    const int nch = (qt >> 3) + 1;
    const int base = (b * NQT + qt) * MAXCH;
    const int tid = threadIdx.x;

    __shared__ float wsh[MAXCH][64];
    __shared__ float invD[64];

    if (tid < 64) {
        int r = tid;
        float mmax = -1e30f;
        for (int c = 0; c < nch; c++)
            mmax = fmaxf(mmax, g_pm[(base + c) * 64 + r]);
        float D = 0.f;
        for (int c = 0; c < nch; c++) {
            float wv = __expf(g_pm[(base + c) * 64 + r] - mmax);
            wsh[c][r] = wv;
            D += wv * g_pl[(base + c) * 64 + r];
        }
        invD[r] = 1.0f / D;
    }
    __syncthreads();

    const int col = tid;   // HD = 128 = blockDim
    for (int r = 0; r < 64; r++) {
        float acc = 0.f;
        for (int c = 0; c < nch; c++)
            acc += wsh[c][r] * g_pO[(size_t)(base + c) * 64 * HD + (size_t)r * HD + col];
        out[((size_t)(b * SEQ + qt * 64 + r)) * HD + col] = acc * invD[r];
    }
}

// ---------------------------------------------------------------------------
extern "C" void kernel_launch(void* const* d_in, const int* in_sizes, int n_in,
                              void* d_out, int out_size)
{
    // Robust input mapping: classify by size (elements or bytes).
    const float* x = (const float*)d_in[0];
    const float* Wp[3] = { (const float*)d_in[1], (const float*)d_in[3], (const float*)d_in[5] };
    const float* bp[3] = { (const float*)d_in[2], (const float*)d_in[4], (const float*)d_in[6] };
    {
        int nw = 0, nb = 0;
        const float* Wt[3]; const float* bt[3]; const float* xt = nullptr;
        for (int i = 0; i < n_in; i++) {
            long long sz = in_sizes[i];
            bool isX = (sz == (long long)BTOT * EMB) || (sz == (long long)BTOT * EMB * 4);
            bool isW = (sz == (long long)EMB * HD)   || (sz == (long long)EMB * HD * 4);
            bool isB = (sz == HD)                    || (sz == HD * 4);
            if (isX)                 xt = (const float*)d_in[i];
            else if (isW && nw < 3)  Wt[nw++] = (const float*)d_in[i];
            else if (isB && nb < 3)  bt[nb++] = (const float*)d_in[i];
        }
        if (xt && nw == 3 && nb == 3) {
            x = xt;
            Wp[0] = Wt[0]; Wp[1] = Wt[1]; Wp[2] = Wt[2];
            bp[0] = bt[0]; bp[1] = bt[1]; bp[2] = bt[2];
        }
    }
    float* out = (float*)d_out;

    cudaFuncSetAttribute(qkv_kernel, cudaFuncAttributeMaxDynamicSharedMemorySize, QKV_SMEM);
    dim3 gq(BTOT / 128, 3);
    qkv_kernel<<<gq, 256, QKV_SMEM>>>(x, Wp[0], bp[0], Wp[1], bp[1], Wp[2], bp[2]);

    cudaFuncSetAttribute(attn_kernel, cudaFuncAttributeMaxDynamicSharedMemorySize, ATTN_SMEM);
    dim3 ga(NQT, MAXCH, BATCH);
    attn_kernel<<<ga, 128, ATTN_SMEM>>>();

    merge_kernel<<<BATCH * NQT, 128>>>(out);
}

// round 12
// speedup vs baseline: 1.0723x; 1.0723x over previous
#include <cuda_runtime.h>
#include <cuda_bf16.h>

#define BATCH 4
#define SEQ   2048
#define EMB   1024
#define HD    128
#define BTOT  (BATCH*SEQ)

#define NQT      32          // q tiles per batch (BQ=64)
#define CHTILES  8           // kv tiles (of 64) per chunk = 512 keys
#define MAXCH    4           // max chunks per q tile
#define NKT      (EMB/32)    // k-tiles in QKV GEMM = 32

// ---------------- device scratch (allocation-free rule) ----------------
__device__ float g_Q[BTOT * HD];   // full fp32
__device__ float g_K[BTOT * HD];   // full fp32
__device__ float g_V[BTOT * HD];   // full fp32
// split-KV partials: slot = ((b*NQT + qt)*MAXCH + c)
__device__ float g_pO[(size_t)BATCH * NQT * MAXCH * 64 * HD];
__device__ float g_pm[BATCH * NQT * MAXCH * 64];
__device__ float g_pl[BATCH * NQT * MAXCH * 64];

__device__ __forceinline__ unsigned f2tf(float f) {
    unsigned u;
    asm("cvt.rna.tf32.f32 %0, %1;" : "=r"(u) : "f"(f));
    return u;
}

// 3xTF32 split: v = hi + lo to ~2^-22 relative
__device__ __forceinline__ void split3(float v, unsigned& hi, unsigned& lo) {
    unsigned h = f2tf(v);
    float r = v - __uint_as_float(h);   // exact in fp32
    hi = h;
    lo = f2tf(r);
}

__device__ __forceinline__ void cp_async16(void* smem_dst, const void* gmem_src) {
    unsigned s = (unsigned)__cvta_generic_to_shared(smem_dst);
    asm volatile("cp.async.cg.shared.global [%0], [%1], 16;\n" :: "r"(s), "l"(gmem_src));
}
__device__ __forceinline__ void cp_commit() {
    asm volatile("cp.async.commit_group;\n");
}
template<int N> __device__ __forceinline__ void cp_wait() {
    asm volatile("cp.async.wait_group %0;\n" :: "n"(N) : "memory");
}

// mma.sync m16n8k8 tf32: A row-major 16x8, B col-major 8x8, C fp32 16x8
__device__ __forceinline__ void mma_tf32(float* c, const unsigned* a, unsigned b0, unsigned b1) {
    asm volatile(
        "mma.sync.aligned.m16n8k8.row.col.f32.tf32.tf32.f32 "
        "{%0,%1,%2,%3}, {%4,%5,%6,%7}, {%8,%9}, {%0,%1,%2,%3};\n"
        : "+f"(c[0]), "+f"(c[1]), "+f"(c[2]), "+f"(c[3])
        : "r"(a[0]), "r"(a[1]), "r"(a[2]), "r"(a[3]), "r"(b0), "r"(b1));
}

// 3xTF32 compensated MMA: c += a*b with a = ah+al, b = bh+bl (al*bl dropped)
__device__ __forceinline__ void mma3(float* c, const unsigned* ah, const unsigned* al,
                                     unsigned bh0, unsigned bh1, unsigned bl0, unsigned bl1) {
    mma_tf32(c, al, bh0, bh1);
    mma_tf32(c, ah, bl0, bl1);
    mma_tf32(c, ah, bh0, bh1);
}

// ---------------------------------------------------------------------------
// Kernel 1: QKV projection, 3xTF32. Tile 64(M) x 128(N), K-chunk 32,
// cp.async double-buffered fp32 staging; hi/lo split at fragment load.
// 256 threads = 8 warps: wm 0..3 -> 16-row strip, wn 0..1 -> 64-col strip.
// Grid (BTOT/64, 3) = 384 CTAs: balances across 148 SMs at occ 2 (vs the
// old 192-CTA layout that left 104 SMs at half load). WS = 136 (== 8 mod 32)
// makes B-fragment LDS bank-conflict-free (bank = 8t + g, bijective).
// ---------------------------------------------------------------------------
#define XS 36
#define WS 136
#define QKV_SMEM ((2*64*XS + 2*32*WS) * 4)   // 53248 B

__global__ void __launch_bounds__(256, 2)
qkv_kernel(const float* __restrict__ x,
           const float* __restrict__ Wq, const float* __restrict__ bq,
           const float* __restrict__ Wk, const float* __restrict__ bk,
           const float* __restrict__ Wv, const float* __restrict__ bv)
{
    extern __shared__ float qsm[];
    float (*xs)[64][XS] = reinterpret_cast<float(*)[64][XS]>(qsm);
    float (*ws)[32][WS] = reinterpret_cast<float(*)[32][WS]>(qsm + 2 * 64 * XS);

    const float* W; const float* bias; float* out;
    if (blockIdx.y == 0)      { W = Wq; bias = bq; out = g_Q; }
    else if (blockIdx.y == 1) { W = Wk; bias = bk; out = g_K; }
    else                      { W = Wv; bias = bv; out = g_V; }

    const int tid  = threadIdx.x;
    const int lane = tid & 31;
    const int warp = tid >> 5;
    const int wm   = warp >> 1;   // 0..3 -> 16-row strip
    const int wn   = warp & 1;    // 0..1 -> 64-col strip
    const int g    = lane >> 2;
    const int t    = lane & 3;
    const int m0   = blockIdx.x * 64;

    float acc[8][4];
#pragma unroll
    for (int j = 0; j < 8; j++)
#pragma unroll
        for (int k = 0; k < 4; k++) acc[j][k] = 0.f;

    auto stage = [&](int kt, int bf) {
        const int kk = kt * 32;
        // x tile 64x32: 512 float4, 2 per thread
#pragma unroll
        for (int j = 0; j < 2; j++) {
            int idx = tid + j * 256;
            int r = idx >> 3, c4 = (idx & 7) * 4;
            cp_async16(&xs[bf][r][c4], &x[(size_t)(m0 + r) * EMB + kk + c4]);
        }
        // W tile 32x128: 1024 float4, 4 per thread
#pragma unroll
        for (int j = 0; j < 4; j++) {
            int idx = tid + j * 256;
            int r = idx >> 5, c4 = (idx & 31) * 4;
            cp_async16(&ws[bf][r][c4], &W[(size_t)(kk + r) * HD + c4]);
        }
        cp_commit();
    };

    stage(0, 0);
    int buf = 0;

    for (int kt = 0; kt < NKT; kt++) {
        if (kt + 1 < NKT) { stage(kt + 1, buf ^ 1); cp_wait<1>(); }
        else              { cp_wait<0>(); }
        __syncthreads();

#pragma unroll
        for (int ks = 0; ks < 32; ks += 8) {
            const int rm = wm * 16;
            unsigned ah[4], al[4];
            split3(xs[buf][rm + g    ][ks + t    ], ah[0], al[0]);
            split3(xs[buf][rm + g + 8][ks + t    ], ah[1], al[1]);
            split3(xs[buf][rm + g    ][ks + t + 4], ah[2], al[2]);
            split3(xs[buf][rm + g + 8][ks + t + 4], ah[3], al[3]);
#pragma unroll
            for (int nt = 0; nt < 8; nt++) {
                int n = wn * 64 + nt * 8 + g;
                unsigned bh0, bl0, bh1, bl1;
                split3(ws[buf][ks + t    ][n], bh0, bl0);
                split3(ws[buf][ks + t + 4][n], bh1, bl1);
                mma3(acc[nt], ah, al, bh0, bh1, bl0, bl1);
            }
        }
        __syncthreads();
        buf ^= 1;
    }

#pragma unroll
    for (int nt = 0; nt < 8; nt++) {
        int row = m0 + wm * 16 + g;
        int col = wn * 64 + nt * 8 + t * 2;
        float b0 = bias[col], b1 = bias[col + 1];
        out[(size_t)row * HD + col]           = acc[nt][0] + b0;
        out[(size_t)row * HD + col + 1]       = acc[nt][1] + b1;
        out[(size_t)(row + 8) * HD + col]     = acc[nt][2] + b0;
        out[(size_t)(row + 8) * HD + col + 1] = acc[nt][3] + b1;
    }
}

// ---------------------------------------------------------------------------
// Kernel 2: split-KV causal flash attention chunk, 3xTF32. BQ=64, BK=64.
// Grid (NQT, MAXCH, BATCH); ch > qt/8 exits. 128 threads (4 warps).
// Q staged once in smem (fp32); K/V staged per tile (fp32); hi/lo split at
// fragment load. P (fp32) overlays the K smem region: K fully consumed by
// the S-phase; a block barrier separates last K read from first P write.
// Smem: K/P 64x132 | V 64x136 | Q 64x132 = 102400 B. Occupancy 2.
// ---------------------------------------------------------------------------
#define KS 132
#define VS 136
#define PS 68
#define ATTN_SMEM ((64*KS + 64*VS + 64*KS) * 4)   // 102400 B

__global__ void __launch_bounds__(128, 2)
attn_kernel()
{
    const int qt = blockIdx.x;
    const int ch = blockIdx.y;
    const int b  = blockIdx.z;
    if (ch > (qt >> 3)) return;   // nch = qt/8 + 1

    extern __shared__ float sm[];
    float (*Ksm)[KS] = reinterpret_cast<float(*)[KS]>(sm);
    float (*Psm)[PS] = reinterpret_cast<float(*)[PS]>(sm);              // overlays K
    float (*Vsm)[VS] = reinterpret_cast<float(*)[VS]>(sm + 64 * KS);
    float (*Qsm)[KS] = reinterpret_cast<float(*)[KS]>(sm + 64 * KS + 64 * VS);

    const int q0    = qt * 64;
    const int kt0   = ch * CHTILES;
    const int ktend = min(kt0 + CHTILES, qt + 1);

    const int tid = threadIdx.x, lane = tid & 31, w = tid >> 5;
    const int g = lane >> 2, t = lane & 3;
    const float scale = 0.08838834764831845f;  // 1/sqrt(128)

    // stage Q tile once (fp32)
    {
        const float* Qg = g_Q + (size_t)(b * SEQ + q0) * HD;
        for (int j = tid; j < 2048; j += 128) {
            int r = j >> 5, c4 = (j & 31) * 4;
            cp_async16(&Qsm[r][c4], &Qg[(size_t)r * HD + c4]);
        }
        cp_commit();
    }

    float m_i[2] = { -1e30f, -1e30f };
    float l_i[2] = { 0.f, 0.f };
    float o[16][4];
#pragma unroll
    for (int i = 0; i < 16; i++)
#pragma unroll
        for (int j = 0; j < 4; j++) o[i][j] = 0.f;

    const float* Kp = g_K + (size_t)(b * SEQ) * HD;
    const float* Vp = g_V + (size_t)(b * SEQ) * HD;

    for (int kt = kt0; kt < ktend; kt++) {
        const int kv0 = kt * 64;
        __syncthreads();   // prior-iteration P/V reads complete before restage
        for (int j = tid; j < 2048; j += 128) {
            int r = j >> 5, c4 = (j & 31) * 4;
            cp_async16(&Ksm[r][c4], &Kp[(size_t)(kv0 + r) * HD + c4]);
            cp_async16(&Vsm[r][c4], &Vp[(size_t)(kv0 + r) * HD + c4]);
        }
        cp_commit();
        cp_wait<0>();      // also covers the Q stage on the first iteration
        __syncthreads();

        // ---- S = Q @ K^T (3xTF32), 16 x 64 per warp ----
        float s[8][4];
#pragma unroll
        for (int nt = 0; nt < 8; nt++)
#pragma unroll
            for (int j = 0; j < 4; j++) s[nt][j] = 0.f;

#pragma unroll
        for (int kc = 0; kc < 16; kc++) {
            const int d0 = kc * 8 + t;
            unsigned ah[4], al[4];
            split3(Qsm[w * 16 + g    ][d0    ], ah[0], al[0]);
            split3(Qsm[w * 16 + g + 8][d0    ], ah[1], al[1]);
            split3(Qsm[w * 16 + g    ][d0 + 4], ah[2], al[2]);
            split3(Qsm[w * 16 + g + 8][d0 + 4], ah[3], al[3]);
#pragma unroll
            for (int nt = 0; nt < 8; nt++) {
                const int key = nt * 8 + g;
                unsigned bh0, bl0, bh1, bl1;
                split3(Ksm[key][d0    ], bh0, bl0);
                split3(Ksm[key][d0 + 4], bh1, bl1);
                mma3(s[nt], ah, al, bh0, bh1, bl0, bl1);
            }
        }

        // apply softmax scale
#pragma unroll
        for (int nt = 0; nt < 8; nt++) {
            s[nt][0] *= scale; s[nt][1] *= scale;
            s[nt][2] *= scale; s[nt][3] *= scale;
        }

        // causal mask on the diagonal tile
        if (kt == qt) {
            int qr = q0 + w * 16 + g;
#pragma unroll
            for (int nt = 0; nt < 8; nt++) {
                int kc0 = kv0 + nt * 8 + t * 2;
                if (kc0     > qr)     s[nt][0] = -1e30f;
                if (kc0 + 1 > qr)     s[nt][1] = -1e30f;
                if (kc0     > qr + 8) s[nt][2] = -1e30f;
                if (kc0 + 1 > qr + 8) s[nt][3] = -1e30f;
            }
        }

        // online softmax
        float mx0 = -1e30f, mx1 = -1e30f;
#pragma unroll
        for (int nt = 0; nt < 8; nt++) {
            mx0 = fmaxf(mx0, fmaxf(s[nt][0], s[nt][1]));
            mx1 = fmaxf(mx1, fmaxf(s[nt][2], s[nt][3]));
        }
        mx0 = fmaxf(mx0, __shfl_xor_sync(0xffffffffu, mx0, 1));
        mx0 = fmaxf(mx0, __shfl_xor_sync(0xffffffffu, mx0, 2));
        mx1 = fmaxf(mx1, __shfl_xor_sync(0xffffffffu, mx1, 1));
        mx1 = fmaxf(mx1, __shfl_xor_sync(0xffffffffu, mx1, 2));

        float mn0 = fmaxf(m_i[0], mx0);
        float mn1 = fmaxf(m_i[1], mx1);
        float a0 = __expf(m_i[0] - mn0);
        float a1 = __expf(m_i[1] - mn1);
        m_i[0] = mn0; m_i[1] = mn1;

        float rs0 = 0.f, rs1 = 0.f;
#pragma unroll
        for (int nt = 0; nt < 8; nt++) {
            s[nt][0] = __expf(s[nt][0] - mn0);
            s[nt][1] = __expf(s[nt][1] - mn0);
            s[nt][2] = __expf(s[nt][2] - mn1);
            s[nt][3] = __expf(s[nt][3] - mn1);
            rs0 += s[nt][0] + s[nt][1];
            rs1 += s[nt][2] + s[nt][3];
        }
        rs0 += __shfl_xor_sync(0xffffffffu, rs0, 1);
        rs0 += __shfl_xor_sync(0xffffffffu, rs0, 2);
        rs1 += __shfl_xor_sync(0xffffffffu, rs1, 1);
        rs1 += __shfl_xor_sync(0xffffffffu, rs1, 2);
        l_i[0] = l_i[0] * a0 + rs0;
        l_i[1] = l_i[1] * a1 + rs1;

#pragma unroll
        for (int nt2 = 0; nt2 < 16; nt2++) {
            o[nt2][0] *= a0; o[nt2][1] *= a0;
            o[nt2][2] *= a1; o[nt2][3] *= a1;
        }

        // All warps done reading K before P overwrites the region
        __syncthreads();

        // P -> smem (warp-private rows), FULL fp32
        {
            int pr = w * 16 + g;
#pragma unroll
            for (int nt = 0; nt < 8; nt++) {
                int pc = nt * 8 + t * 2;
                Psm[pr    ][pc    ] = s[nt][0];
                Psm[pr    ][pc + 1] = s[nt][1];
                Psm[pr + 8][pc    ] = s[nt][2];
                Psm[pr + 8][pc + 1] = s[nt][3];
            }
        }
        __syncwarp();

        // ---- O += P @ V (3xTF32) ----
#pragma unroll
        for (int cc = 0; cc < 8; cc++) {
            const int pk = cc * 8 + t;
            unsigned pah[4], pal[4];
            split3(Psm[w * 16 + g    ][pk    ], pah[0], pal[0]);
            split3(Psm[w * 16 + g + 8][pk    ], pah[1], pal[1]);
            split3(Psm[w * 16 + g    ][pk + 4], pah[2], pal[2]);
            split3(Psm[w * 16 + g + 8][pk + 4], pah[3], pal[3]);
#pragma unroll
            for (int nt2 = 0; nt2 < 16; nt2++) {
                const int d = nt2 * 8 + g;
                unsigned bh0, bl0, bh1, bl1;
                split3(Vsm[cc * 8 + t    ][d], bh0, bl0);
                split3(Vsm[cc * 8 + t + 4][d], bh1, bl1);
                mma3(o[nt2], pah, pal, bh0, bh1, bl0, bl1);
            }
        }
        __syncwarp();
    }

    // write partials (unnormalized O, plus m and l)
    const int slot = (b * NQT + qt) * MAXCH + ch;
    float* pO = g_pO + (size_t)slot * 64 * HD;
#pragma unroll
    for (int nt2 = 0; nt2 < 16; nt2++) {
        int col = nt2 * 8 + t * 2;
        int r0 = w * 16 + g;
        pO[(size_t)r0 * HD + col]           = o[nt2][0];
        pO[(size_t)r0 * HD + col + 1]       = o[nt2][1];
        pO[(size_t)(r0 + 8) * HD + col]     = o[nt2][2];
        pO[(size_t)(r0 + 8) * HD + col + 1] = o[nt2][3];
    }
    if (t == 0) {
        g_pm[slot * 64 + w * 16 + g]     = m_i[0];
        g_pm[slot * 64 + w * 16 + g + 8] = m_i[1];
        g_pl[slot * 64 + w * 16 + g]     = l_i[0];
        g_pl[slot * 64 + w * 16 + g + 8] = l_i[1];
    }
}

// ---------------------------------------------------------------------------
// Kernel 3: merge split-KV partials for ALL q tiles. One block per (b, qt).
// out = sum_c exp(m_c - M) * O_c / sum_c exp(m_c - M) * l_c
// ---------------------------------------------------------------------------
__global__ void __launch_bounds__(128)
merge_kernel(float* __restrict__ out)
{
    const int b  = blockIdx.x >> 5;
    const int qt = blockIdx.x & 31;
    const int nch = (qt >> 3) + 1;
    const int base = (b * NQT + qt) * MAXCH;
    const int tid = threadIdx.x;

    __shared__ float wsh[MAXCH][64];
    __shared__ float invD[64];

    if (tid < 64) {
        int r = tid;
        float mmax = -1e30f;
        for (int c = 0; c < nch; c++)
            mmax = fmaxf(mmax, g_pm[(base + c) * 64 + r]);
        float D = 0.f;
        for (int c = 0; c < nch; c++) {
            float wv = __expf(g_pm[(base + c) * 64 + r] - mmax);
            wsh[c][r] = wv;
            D += wv * g_pl[(base + c) * 64 + r];
        }
        invD[r] = 1.0f / D;
    }
    __syncthreads();

    const int col = tid;   // HD = 128 = blockDim
    for (int r = 0; r < 64; r++) {
        float acc = 0.f;
        for (int c = 0; c < nch; c++)
            acc += wsh[c][r] * g_pO[(size_t)(base + c) * 64 * HD + (size_t)r * HD + col];
        out[((size_t)(b * SEQ + qt * 64 + r)) * HD + col] = acc * invD[r];
    }
}

// ---------------------------------------------------------------------------
extern "C" void kernel_launch(void* const* d_in, const int* in_sizes, int n_in,
                              void* d_out, int out_size)
{
    // Robust input mapping: classify by size (elements or bytes).
    const float* x = (const float*)d_in[0];
    const float* Wp[3] = { (const float*)d_in[1], (const float*)d_in[3], (const float*)d_in[5] };
    const float* bp[3] = { (const float*)d_in[2], (const float*)d_in[4], (const float*)d_in[6] };
    {
        int nw = 0, nb = 0;
        const float* Wt[3]; const float* bt[3]; const float* xt = nullptr;
        for (int i = 0; i < n_in; i++) {
            long long sz = in_sizes[i];
            bool isX = (sz == (long long)BTOT * EMB) || (sz == (long long)BTOT * EMB * 4);
            bool isW = (sz == (long long)EMB * HD)   || (sz == (long long)EMB * HD * 4);
            bool isB = (sz == HD)                    || (sz == HD * 4);
            if (isX)                 xt = (const float*)d_in[i];
            else if (isW && nw < 3)  Wt[nw++] = (const float*)d_in[i];
            else if (isB && nb < 3)  bt[nb++] = (const float*)d_in[i];
        }
        if (xt && nw == 3 && nb == 3) {
            x = xt;
            Wp[0] = Wt[0]; Wp[1] = Wt[1]; Wp[2] = Wt[2];
            bp[0] = bt[0]; bp[1] = bt[1]; bp[2] = bt[2];
        }
    }
    float* out = (float*)d_out;

    cudaFuncSetAttribute(qkv_kernel, cudaFuncAttributeMaxDynamicSharedMemorySize, QKV_SMEM);
    dim3 gq(BTOT / 64, 3);
    qkv_kernel<<<gq, 256, QKV_SMEM>>>(x, Wp[0], bp[0], Wp[1], bp[1], Wp[2], bp[2]);

    cudaFuncSetAttribute(attn_kernel, cudaFuncAttributeMaxDynamicSharedMemorySize, ATTN_SMEM);
    dim3 ga(NQT, MAXCH, BATCH);
    attn_kernel<<<ga, 128, ATTN_SMEM>>>();

    merge_kernel<<<BATCH * NQT, 128>>>(out);
}